// round 1
// baseline (speedup 1.0000x reference)
#include <cuda_runtime.h>
#include <math.h>

#define T_TREES 200
#define BATCH   2048
#define D_FEAT  512
#define NNODE   64
#define NLEAF   15
#define NLEAVES 16
#define LR      0.01f

#define BM 64     // batch rows per block
#define BK 16     // K chunk

// Scratch for per-tree leaf scores f[t][b]  (200*2048*4 = 1.6 MB)
__device__ float g_f[T_TREES * BATCH];

struct SmemLayout {
    float xs[BM][BK + 1];          // x tile       (padded)
    float ws[BK][NNODE];           // w_t tile
    float h [BM][NNODE + 1];       // relu output  (padded)
    float wds[NNODE * NLEAF];      // w_d for this tree
    float ps[BM][NLEAVES + 1];     // sigmoid probs (padded, 15 used)
    float wls[NLEAVES];
    float bds[NLEAF];
};

__device__ __forceinline__ float sigmoidf_(float v) {
    return 1.0f / (1.0f + expf(-v));
}

__global__ __launch_bounds__(256, 2)
void gbdt_tree_kernel(const float* __restrict__ x,
                      const float* __restrict__ w_t,
                      const float* __restrict__ b_t,
                      const float* __restrict__ w_d,
                      const float* __restrict__ b_d,
                      const float* __restrict__ w_l,
                      const float* __restrict__ b_l)
{
    __shared__ SmemLayout s;

    const int t   = blockIdx.y;          // tree index
    const int rb  = blockIdx.x * BM;     // batch row base
    const int tid = threadIdx.x;
    const int tx  = tid & 15;            // 0..15 (node micro-tile)
    const int ty  = tid >> 4;            // 0..15 (row micro-tile)

    // ---------------- Stage 1: h = relu(x @ w_t[t] + b_t[t]) ----------------
    float acc[4][4];
    #pragma unroll
    for (int i = 0; i < 4; i++)
        #pragma unroll
        for (int j = 0; j < 4; j++) acc[i][j] = 0.0f;

    const float* wt = w_t + (size_t)t * D_FEAT * NNODE;

    for (int kc = 0; kc < D_FEAT; kc += BK) {
        // load x tile [BM][BK]
        #pragma unroll
        for (int i = tid; i < BM * BK; i += 256) {
            int r = i >> 4;       // /BK
            int k = i & (BK - 1);
            s.xs[r][k] = x[(size_t)(rb + r) * D_FEAT + kc + k];
        }
        // load w_t tile [BK][NNODE]  (contiguous in n -> coalesced)
        #pragma unroll
        for (int i = tid; i < BK * NNODE; i += 256) {
            int k = i >> 6;       // /NNODE
            int n = i & (NNODE - 1);
            s.ws[k][n] = wt[(size_t)(kc + k) * NNODE + n];
        }
        __syncthreads();

        #pragma unroll
        for (int kk = 0; kk < BK; kk++) {
            float a[4], bw[4];
            #pragma unroll
            for (int i = 0; i < 4; i++) a[i]  = s.xs[ty * 4 + i][kk];
            #pragma unroll
            for (int j = 0; j < 4; j++) bw[j] = s.ws[kk][tx * 4 + j];
            #pragma unroll
            for (int i = 0; i < 4; i++)
                #pragma unroll
                for (int j = 0; j < 4; j++)
                    acc[i][j] = fmaf(a[i], bw[j], acc[i][j]);
        }
        __syncthreads();
    }

    // bias + relu -> smem h
    #pragma unroll
    for (int j = 0; j < 4; j++) {
        int n = tx * 4 + j;
        float bias = b_t[t * NNODE + n];
        #pragma unroll
        for (int i = 0; i < 4; i++) {
            float v = acc[i][j] + bias;
            s.h[ty * 4 + i][n] = fmaxf(v, 0.0f);
        }
    }

    // load per-tree decision weights
    for (int i = tid; i < NNODE * NLEAF; i += 256)
        s.wds[i] = w_d[(size_t)t * NNODE * NLEAF + i];
    if (tid < NLEAF)   s.bds[tid] = b_d[t * NLEAF + tid];
    if (tid < NLEAVES) s.wls[tid] = w_l[t * NLEAVES + tid];
    __syncthreads();

    // ---------------- Stage 2: p = sigmoid(h @ w_d + b_d)  [BM x 15] --------
    {
        const int row = tid >> 2;   // 0..63
        const int j   = tid & 3;    // node strided by 4: j, j+4, j+8, (j+12)
        float a0 = 0.f, a1 = 0.f, a2 = 0.f, a3 = 0.f;
        #pragma unroll 8
        for (int k = 0; k < NNODE; k++) {
            float hv = s.h[row][k];
            const float* wrow = &s.wds[k * NLEAF];
            a0 = fmaf(hv, wrow[j],     a0);
            a1 = fmaf(hv, wrow[j + 4], a1);
            a2 = fmaf(hv, wrow[j + 8], a2);
            if (j < 3) a3 = fmaf(hv, wrow[j + 12], a3);
        }
        s.ps[row][j]     = sigmoidf_(a0 + s.bds[j]);
        s.ps[row][j + 4] = sigmoidf_(a1 + s.bds[j + 4]);
        s.ps[row][j + 8] = sigmoidf_(a2 + s.bds[j + 8]);
        if (j < 3) s.ps[row][j + 12] = sigmoidf_(a3 + s.bds[j + 12]);
    }
    __syncthreads();

    // ---------------- Stage 3: routing products + tanh leaf score -----------
    if (tid < BM) {
        const int row = tid;
        float facc = 0.0f;
        #pragma unroll
        for (int l = 0; l < NLEAVES; l++) {
            int node = 0;
            float m = 1.0f;
            #pragma unroll
            for (int d = 0; d < 4; d++) {
                int bit = (l >> (3 - d)) & 1;
                float pv = s.ps[row][node];
                m *= bit ? (1.0f - pv) : pv;
                node = 2 * node + 1 + bit;
            }
            facc = fmaf(m, s.wls[l], facc);
        }
        float f = tanhf(facc + b_l[t]);
        g_f[(size_t)t * BATCH + rb + row] = f;
    }
}

// ---------------- Kernel 2: sequential boosting cumsum -----------------------
__global__ void gbdt_cumsum_kernel(const float* __restrict__ f0,
                                   float* __restrict__ out)
{
    int b = blockIdx.x * blockDim.x + threadIdx.x;
    if (b >= BATCH) return;
    float run = f0[0];
    out[(size_t)b * (T_TREES + 1)] = run;
    #pragma unroll 4
    for (int t = 0; t < T_TREES; t++) {
        run += LR * g_f[(size_t)t * BATCH + b];
        out[(size_t)b * (T_TREES + 1) + t + 1] = run;
    }
}

extern "C" void kernel_launch(void* const* d_in, const int* in_sizes, int n_in,
                              void* d_out, int out_size)
{
    // metadata order: x, y_true, w_t, b_t, w_d, b_d, w_l, b_l, f_0
    const float* x   = (const float*)d_in[0];
    // d_in[1] = y_true (unused at inference)
    const float* w_t = (const float*)d_in[2];
    const float* b_t = (const float*)d_in[3];
    const float* w_d = (const float*)d_in[4];
    const float* b_d = (const float*)d_in[5];
    const float* w_l = (const float*)d_in[6];
    const float* b_l = (const float*)d_in[7];
    const float* f_0 = (const float*)d_in[8];
    float* out = (float*)d_out;

    dim3 grid(BATCH / BM, T_TREES);
    gbdt_tree_kernel<<<grid, 256>>>(x, w_t, b_t, w_d, b_d, w_l, b_l);
    gbdt_cumsum_kernel<<<(BATCH + 255) / 256, 256>>>(f_0, out);
}

// round 3
// speedup vs baseline: 7.2219x; 7.2219x over previous
#include <cuda_runtime.h>
#include <cuda_bf16.h>
#include <cstdint>
#include <math.h>

#define T_TREES 200
#define BATCH   2048
#define D_FEAT  512
#define NNODE   64
#define NLEAF   15
#define NLEAVES 16
#define LR      0.01f

// ---------------- device scratch (no runtime allocation allowed) -------------
__device__ __nv_bfloat16 g_xbf[BATCH * D_FEAT];                   // x in bf16
__device__ __nv_bfloat16 g_wbf[(size_t)T_TREES * NNODE * D_FEAT]; // w_t bf16, [t][n][k]
__device__ float g_fT[(size_t)BATCH * T_TREES];                   // f transposed [b][t]

// ---------------- helpers ------------------------------------------------------
__device__ __forceinline__ uint32_t smem_u32(const void* p) {
    uint32_t a;
    asm("{ .reg .u64 t; cvta.to.shared.u64 t, %1; cvt.u32.u64 %0, t; }" : "=r"(a) : "l"(p));
    return a;
}
#define SWZ(o) ((o) ^ (((o) >> 3) & 0x70))

__device__ __forceinline__ void cp16(uint32_t dst, const void* src) {
    asm volatile("cp.async.cg.shared.global [%0], [%1], 16;" :: "r"(dst), "l"(src));
}
#define CP_COMMIT() asm volatile("cp.async.commit_group;")
#define CP_WAIT0()  asm volatile("cp.async.wait_group 0;")

#define LDSM_X4(r, addr) \
    asm volatile("ldmatrix.sync.aligned.m8n8.x4.shared.b16 {%0,%1,%2,%3}, [%4];" \
        : "=r"((r)[0]), "=r"((r)[1]), "=r"((r)[2]), "=r"((r)[3]) : "r"(addr))

#define MMA_BF16(d, a, b) \
    asm volatile("mma.sync.aligned.m16n8k16.row.col.f32.bf16.bf16.f32 " \
        "{%0,%1,%2,%3}, {%4,%5,%6,%7}, {%8,%9}, {%0,%1,%2,%3};" \
        : "+f"((d)[0]), "+f"((d)[1]), "+f"((d)[2]), "+f"((d)[3]) \
        : "r"((a)[0]), "r"((a)[1]), "r"((a)[2]), "r"((a)[3]), \
          "r"((b)[0]), "r"((b)[1]))

// ---------------- prep kernels ------------------------------------------------
__global__ void conv_x_kernel(const float* __restrict__ x) {
    int i = (blockIdx.x * blockDim.x + threadIdx.x) * 4;
    float4 v = *(const float4*)(x + i);
    *(__nv_bfloat162*)(g_xbf + i)     = __floats2bfloat162_rn(v.x, v.y);
    *(__nv_bfloat162*)(g_xbf + i + 2) = __floats2bfloat162_rn(v.z, v.w);
}

// transpose w_t[t][k][n] (fp32) -> g_wbf[t][n][k] (bf16)
__global__ void conv_w_kernel(const float* __restrict__ w_t) {
    __shared__ float tile[64][65];
    int t = blockIdx.y, kb = blockIdx.x * 64;
    const float* src = w_t + ((size_t)t * D_FEAT + kb) * NNODE;
    for (int i = threadIdx.x; i < 64 * 64; i += 256) {
        int r = i >> 6, n = i & 63;
        tile[r][n] = src[r * NNODE + n];
    }
    __syncthreads();
    __nv_bfloat16* dst = g_wbf + (size_t)t * NNODE * D_FEAT;
    for (int i = threadIdx.x; i < 64 * 64; i += 256) {
        int n = i >> 6, kk = i & 63;
        dst[(size_t)n * D_FEAT + kb + kk] = __float2bfloat16(tile[kk][n]);
    }
}

// ---------------- main fused kernel -------------------------------------------
// grid (16, 200), 128 threads (4 warps). CTA: tree t, batch rows [rb, rb+128).
// Stage 1 GEMM: [128 x 512] (bf16) @ [512 x 64] (bf16) -> fp32, via mma.sync.
// Each warp: rows wid*32..wid*32+31, all 64 cols. K chunked by 64.
__global__ void __launch_bounds__(128)
gbdt_main_kernel(const float* __restrict__ b_t, const float* __restrict__ w_d,
                 const float* __restrict__ b_d, const float* __restrict__ w_l,
                 const float* __restrict__ b_l)
{
    __shared__ union {
        struct {
            __nv_bfloat16 A[128 * 64];   // 16 KB, SW128-swizzled 128B rows
            __nv_bfloat16 B[64 * 64];    //  8 KB
        } tiles;
        float h[128 * 65];               // ~33 KB, reused post-GEMM
    } u;
    __shared__ float s_bt[NNODE];
    __shared__ float s_wd[NNODE * NLEAF];
    __shared__ float s_bd[NLEAF];
    __shared__ float s_wl[NLEAVES];

    const int t    = blockIdx.y;
    const int rb   = blockIdx.x * 128;
    const int tid  = threadIdx.x;
    const int wid  = tid >> 5;
    const int lane = tid & 31;

    // per-tree small weights
    if (tid < NNODE) s_bt[tid] = b_t[t * NNODE + tid];
    for (int i = tid; i < NNODE * NLEAF; i += 128) s_wd[i] = w_d[(size_t)t * NNODE * NLEAF + i];
    if (tid < NLEAF)   s_bd[tid] = b_d[t * NLEAF + tid];
    if (tid < NLEAVES) s_wl[tid] = w_l[t * NLEAVES + tid];

    const uint32_t aBase = smem_u32(u.tiles.A);
    const uint32_t bBase = smem_u32(u.tiles.B);

    float acc[2][8][4];
    #pragma unroll
    for (int mt = 0; mt < 2; mt++)
        #pragma unroll
        for (int nt = 0; nt < 8; nt++)
            #pragma unroll
            for (int r = 0; r < 4; r++) acc[mt][nt][r] = 0.0f;

    // precompute ldmatrix lane addresses (chunk-invariant parts)
    const int a_row = wid * 32 + (lane & 15);          // + mt*16
    const int a_col = (lane >> 4) << 3;                // + kk
    const int b_row = (lane & 7) + ((lane >> 4) << 3); // + nq*16
    const int b_col = ((lane >> 3) & 1) << 3;          // + kk

    for (int c = 0; c < 8; c++) {
        const int kc = c * 64;
        // ---- A tile: x rows [rb, rb+128), k [kc, kc+64)
        const __nv_bfloat16* gx = g_xbf + (size_t)rb * D_FEAT + kc;
        #pragma unroll
        for (int it = 0; it < 8; it++) {
            int ui = tid + it * 128;
            int r = ui >> 3, seg = ui & 7;
            cp16(aBase + SWZ(r * 128 + seg * 16), gx + (size_t)r * D_FEAT + seg * 8);
        }
        // ---- B tile: w rows n [0,64), k [kc, kc+64)
        const __nv_bfloat16* gw = g_wbf + (size_t)t * NNODE * D_FEAT + kc;
        #pragma unroll
        for (int it = 0; it < 4; it++) {
            int ui = tid + it * 128;
            int r = ui >> 3, seg = ui & 7;
            cp16(bBase + SWZ(r * 128 + seg * 16), gw + (size_t)r * D_FEAT + seg * 8);
        }
        CP_COMMIT();
        CP_WAIT0();
        __syncthreads();

        #pragma unroll
        for (int ks = 0; ks < 4; ks++) {
            const int kk = ks * 16;
            uint32_t afr[2][4];
            #pragma unroll
            for (int mt = 0; mt < 2; mt++) {
                uint32_t ad = aBase + SWZ((a_row + mt * 16) * 128 + (a_col + kk) * 2);
                LDSM_X4(afr[mt], ad);
            }
            uint32_t bfr[8][2];
            #pragma unroll
            for (int nq = 0; nq < 4; nq++) {
                uint32_t r4[4];
                uint32_t bd = bBase + SWZ((b_row + nq * 16) * 128 + (b_col + kk) * 2);
                LDSM_X4(r4, bd);
                bfr[2 * nq][0]     = r4[0]; bfr[2 * nq][1]     = r4[1];
                bfr[2 * nq + 1][0] = r4[2]; bfr[2 * nq + 1][1] = r4[3];
            }
            #pragma unroll
            for (int mt = 0; mt < 2; mt++)
                #pragma unroll
                for (int nt = 0; nt < 8; nt++)
                    MMA_BF16(acc[mt][nt], afr[mt], bfr[nt]);
        }
        __syncthreads();   // protect tiles before next chunk's cp.async
    }

    // ---------------- epilogue: bias + relu -> smem h -------------------------
    #pragma unroll
    for (int mt = 0; mt < 2; mt++) {
        int row0 = wid * 32 + mt * 16 + (lane >> 2);
        #pragma unroll
        for (int nt = 0; nt < 8; nt++) {
            int col0 = nt * 8 + (lane & 3) * 2;
            u.h[row0 * 65 + col0]           = fmaxf(acc[mt][nt][0] + s_bt[col0],     0.0f);
            u.h[row0 * 65 + col0 + 1]       = fmaxf(acc[mt][nt][1] + s_bt[col0 + 1], 0.0f);
            u.h[(row0 + 8) * 65 + col0]     = fmaxf(acc[mt][nt][2] + s_bt[col0],     0.0f);
            u.h[(row0 + 8) * 65 + col0 + 1] = fmaxf(acc[mt][nt][3] + s_bt[col0 + 1], 0.0f);
        }
    }
    __syncthreads();

    // ---------------- stage 2: p = sigmoid(h @ w_d + b_d), one row per thread --
    const float* hrow = &u.h[tid * 65];
    float p[NLEAF];
    #pragma unroll
    for (int j = 0; j < NLEAF; j++) p[j] = s_bd[j];
    #pragma unroll
    for (int k = 0; k < NNODE; k++) {
        float hv = hrow[k];
        #pragma unroll
        for (int j = 0; j < NLEAF; j++) p[j] = fmaf(hv, s_wd[k * NLEAF + j], p[j]);
    }
    #pragma unroll
    for (int j = 0; j < NLEAF; j++) p[j] = 1.0f / (1.0f + __expf(-p[j]));

    // ---------------- stage 3: soft routing + tanh ----------------------------
    float facc = 0.0f;
    #pragma unroll
    for (int l = 0; l < NLEAVES; l++) {
        int node = 0;
        float m = 1.0f;
        #pragma unroll
        for (int d = 0; d < 4; d++) {
            int bit = (l >> (3 - d)) & 1;
            float pv = p[node];
            m *= bit ? (1.0f - pv) : pv;
            node = 2 * node + 1 + bit;
        }
        facc = fmaf(m, s_wl[l], facc);
    }
    float f = tanhf(facc + b_l[t]);
    g_fT[(size_t)(rb + tid) * T_TREES + t] = f;
}

// ---------------- cumsum: one warp per batch row -------------------------------
__global__ void gbdt_cumsum_kernel(const float* __restrict__ f0,
                                   float* __restrict__ out)
{
    int gwarp = (blockIdx.x * blockDim.x + threadIdx.x) >> 5;
    int lane  = threadIdx.x & 31;
    if (gwarp >= BATCH) return;
    float run = f0[0];
    if (lane == 0) out[(size_t)gwarp * (T_TREES + 1)] = run;
    for (int base = 0; base < T_TREES; base += 32) {
        int tt = base + lane;
        float v = (tt < T_TREES) ? LR * g_fT[(size_t)gwarp * T_TREES + tt] : 0.0f;
        #pragma unroll
        for (int off = 1; off < 32; off <<= 1) {
            float nv = __shfl_up_sync(0xFFFFFFFFu, v, off);
            if (lane >= off) v += nv;
        }
        if (tt < T_TREES) out[(size_t)gwarp * (T_TREES + 1) + 1 + tt] = run + v;
        run += __shfl_sync(0xFFFFFFFFu, v, 31);
    }
}

// ---------------- launcher ------------------------------------------------------
extern "C" void kernel_launch(void* const* d_in, const int* in_sizes, int n_in,
                              void* d_out, int out_size)
{
    const float* x   = (const float*)d_in[0];
    const float* w_t = (const float*)d_in[2];
    const float* b_t = (const float*)d_in[3];
    const float* w_d = (const float*)d_in[4];
    const float* b_d = (const float*)d_in[5];
    const float* w_l = (const float*)d_in[6];
    const float* b_l = (const float*)d_in[7];
    const float* f_0 = (const float*)d_in[8];
    float* out = (float*)d_out;

    conv_x_kernel<<<(BATCH * D_FEAT / 4 + 255) / 256, 256>>>(x);
    conv_w_kernel<<<dim3(D_FEAT / 64, T_TREES), 256>>>(w_t);
    gbdt_main_kernel<<<dim3(BATCH / 128, T_TREES), 128>>>(b_t, w_d, b_d, w_l, b_l);
    gbdt_cumsum_kernel<<<(BATCH * 32 + 255) / 256, 256>>>(f_0, out);
}

// round 4
// speedup vs baseline: 7.6860x; 1.0643x over previous
#include <cuda_runtime.h>
#include <cuda_bf16.h>
#include <cuda_fp8.h>
#include <cstdint>
#include <math.h>

#define T_TREES 200
#define BATCH   2048
#define D_FEAT  512
#define NNODE   64
#define NLEAF   15
#define NLEAVES 16
#define LR      0.01f

#define W_SCALE 16.0f
#define W_INV   0.0625f

// ---------------- device scratch (no runtime allocation allowed) -------------
__device__ uint8_t g_xf8[BATCH * D_FEAT];                    // x in e4m3
__device__ uint8_t g_wf8[(size_t)T_TREES * NNODE * D_FEAT];  // w_t e4m3, [t][n][k], x16
__device__ float   g_fT[(size_t)BATCH * T_TREES];            // f transposed [b][t]

// ---------------- helpers ------------------------------------------------------
__device__ __forceinline__ uint32_t smem_u32(const void* p) {
    uint32_t a;
    asm("{ .reg .u64 t; cvta.to.shared.u64 t, %1; cvt.u32.u64 %0, t; }" : "=r"(a) : "l"(p));
    return a;
}
#define SWZ(o) ((o) ^ (((o) >> 3) & 0x70))

__device__ __forceinline__ void cp16(uint32_t dst, const void* src) {
    asm volatile("cp.async.cg.shared.global [%0], [%1], 16;" :: "r"(dst), "l"(src));
}
#define CP_COMMIT() asm volatile("cp.async.commit_group;")

#define LDSM_X4(r, addr) \
    asm volatile("ldmatrix.sync.aligned.m8n8.x4.shared.b16 {%0,%1,%2,%3}, [%4];" \
        : "=r"((r)[0]), "=r"((r)[1]), "=r"((r)[2]), "=r"((r)[3]) : "r"(addr))

#define MMA_FP8(d, a, b) \
    asm volatile("mma.sync.aligned.m16n8k32.row.col.f32.e4m3.e4m3.f32 " \
        "{%0,%1,%2,%3}, {%4,%5,%6,%7}, {%8,%9}, {%0,%1,%2,%3};" \
        : "+f"((d)[0]), "+f"((d)[1]), "+f"((d)[2]), "+f"((d)[3]) \
        : "r"((a)[0]), "r"((a)[1]), "r"((a)[2]), "r"((a)[3]), \
          "r"((b)[0]), "r"((b)[1]))

__device__ __forceinline__ float fast_sigmoid(float v) {
    float th;
    asm("tanh.approx.f32 %0, %1;" : "=f"(th) : "f"(v * 0.5f));
    return fmaf(0.5f, th, 0.5f);
}

__device__ __forceinline__ uint16_t pack_e4m3x2(float lo, float hi) {
    float2 f2; f2.x = lo; f2.y = hi;
    return (uint16_t)__nv_cvt_float2_to_fp8x2(f2, __NV_SATFINITE, __NV_E4M3);
}

// ---------------- prep kernels ------------------------------------------------
__global__ void conv_x_kernel(const float* __restrict__ x) {
    int i = (blockIdx.x * blockDim.x + threadIdx.x) * 8;
    float4 v0 = *(const float4*)(x + i);
    float4 v1 = *(const float4*)(x + i + 4);
    uint32_t lo = (uint32_t)pack_e4m3x2(v0.x, v0.y) | ((uint32_t)pack_e4m3x2(v0.z, v0.w) << 16);
    uint32_t hi = (uint32_t)pack_e4m3x2(v1.x, v1.y) | ((uint32_t)pack_e4m3x2(v1.z, v1.w) << 16);
    *(uint2*)(g_xf8 + i) = make_uint2(lo, hi);
}

// transpose w_t[t][k][n] (fp32) -> g_wf8[t][n][k] (e4m3, scaled x16)
__global__ void conv_w_kernel(const float* __restrict__ w_t) {
    __shared__ float tile[64][65];
    int t = blockIdx.y, kb = blockIdx.x * 64;
    const float* src = w_t + ((size_t)t * D_FEAT + kb) * NNODE;
    for (int i = threadIdx.x; i < 64 * 64; i += 256) {
        int r = i >> 6, n = i & 63;
        tile[r][n] = src[r * NNODE + n];
    }
    __syncthreads();
    for (int i = threadIdx.x; i < 64 * 16; i += 256) {
        int n = i >> 4, kq = (i & 15) * 4;
        uint32_t w = (uint32_t)pack_e4m3x2(tile[kq][n] * W_SCALE, tile[kq + 1][n] * W_SCALE)
                   | ((uint32_t)pack_e4m3x2(tile[kq + 2][n] * W_SCALE, tile[kq + 3][n] * W_SCALE) << 16);
        *(uint32_t*)(g_wf8 + ((size_t)t * NNODE + n) * D_FEAT + kb + kq) = w;
    }
}

// ---------------- main fused kernel -------------------------------------------
// grid (16, 200), 128 threads (4 warps). CTA: tree t, batch rows [rb, rb+128).
// GEMM [128 x 512] e4m3 @ [512 x 64] e4m3 -> fp32 via mma.sync.m16n8k32.
// K = 512 bytes in 4 chunks of 128B, double-buffered cp.async.
#define STAGE_BYTES 24576   // A 16KB + B 8KB
#define SMEM_DYN (2 * STAGE_BYTES)

__global__ void __launch_bounds__(128)
gbdt_main_kernel(const float* __restrict__ b_t, const float* __restrict__ w_d,
                 const float* __restrict__ b_d, const float* __restrict__ w_l,
                 const float* __restrict__ b_l)
{
    extern __shared__ char ds[];
    __shared__ float s_bt[NNODE];
    __shared__ float s_wd[NNODE * NLEAF];
    __shared__ float s_bd[NLEAF];
    __shared__ float s_wl[NLEAVES];

    const int t    = blockIdx.y;
    const int rb   = blockIdx.x * 128;
    const int tid  = threadIdx.x;
    const int wid  = tid >> 5;
    const int lane = tid & 31;
    const uint32_t dsBase = smem_u32(ds);

    // per-tree small weights
    if (tid < NNODE) s_bt[tid] = b_t[t * NNODE + tid];
    for (int i = tid; i < NNODE * NLEAF; i += 128) s_wd[i] = w_d[(size_t)t * NNODE * NLEAF + i];
    if (tid < NLEAF)   s_bd[tid] = b_d[t * NLEAF + tid];
    if (tid < NLEAVES) s_wl[tid] = w_l[t * NLEAVES + tid];

    float acc[2][8][4];
    #pragma unroll
    for (int mt = 0; mt < 2; mt++)
        #pragma unroll
        for (int nt = 0; nt < 8; nt++)
            #pragma unroll
            for (int r = 0; r < 4; r++) acc[mt][nt][r] = 0.0f;

    // ldmatrix lane addressing (bytes; 128B rows)
    const int a_row  = wid * 32 + (lane & 15);
    const int a_colb = (lane >> 4) * 16;
    const int b_row  = (lane & 7) + ((lane >> 4) << 3);
    const int b_colb = ((lane >> 3) & 1) * 16;

    const uint8_t* gx = g_xf8 + (size_t)rb * D_FEAT;
    const uint8_t* gw = g_wf8 + (size_t)t * NNODE * D_FEAT;

    // chunk load: A rows 128 x 128B, B rows 64 x 128B into stage c&1
    auto loadChunk = [&](int c) {
        const uint32_t aB = dsBase + (c & 1) * STAGE_BYTES;
        const uint32_t bB = aB + 16384;
        const int kc = c * 128;
        #pragma unroll
        for (int it = 0; it < 8; it++) {
            int ui = tid + it * 128;
            int r = ui >> 3, seg = ui & 7;
            cp16(aB + SWZ(r * 128 + seg * 16), gx + (size_t)r * D_FEAT + kc + seg * 16);
        }
        #pragma unroll
        for (int it = 0; it < 4; it++) {
            int ui = tid + it * 128;
            int r = ui >> 3, seg = ui & 7;
            cp16(bB + SWZ(r * 128 + seg * 16), gw + (size_t)r * D_FEAT + kc + seg * 16);
        }
        CP_COMMIT();
    };

    loadChunk(0);
    for (int c = 0; c < 4; c++) {
        if (c < 3) {
            loadChunk(c + 1);
            asm volatile("cp.async.wait_group 1;");
        } else {
            asm volatile("cp.async.wait_group 0;");
        }
        __syncthreads();

        const uint32_t aB = dsBase + (c & 1) * STAGE_BYTES;
        const uint32_t bB = aB + 16384;
        #pragma unroll
        for (int ks = 0; ks < 4; ks++) {
            const int kk = ks * 32;
            uint32_t afr[2][4];
            #pragma unroll
            for (int mt = 0; mt < 2; mt++)
                LDSM_X4(afr[mt], aB + SWZ((a_row + mt * 16) * 128 + kk + a_colb));
            uint32_t bfr[8][2];
            #pragma unroll
            for (int nq = 0; nq < 4; nq++) {
                uint32_t r4[4];
                LDSM_X4(r4, bB + SWZ((b_row + nq * 16) * 128 + kk + b_colb));
                bfr[2 * nq][0]     = r4[0]; bfr[2 * nq][1]     = r4[1];
                bfr[2 * nq + 1][0] = r4[2]; bfr[2 * nq + 1][1] = r4[3];
            }
            #pragma unroll
            for (int mt = 0; mt < 2; mt++)
                #pragma unroll
                for (int nt = 0; nt < 8; nt++)
                    MMA_FP8(acc[mt][nt], afr[mt], bfr[nt]);
        }
        __syncthreads();   // stage reuse safety
    }

    // ---------------- epilogue: bias + relu -> smem h (overlays tiles) --------
    float* hsm = (float*)ds;   // 128 x 65 floats = 33.3 KB <= 48 KB
    #pragma unroll
    for (int mt = 0; mt < 2; mt++) {
        int row0 = wid * 32 + mt * 16 + (lane >> 2);
        #pragma unroll
        for (int nt = 0; nt < 8; nt++) {
            int col0 = nt * 8 + (lane & 3) * 2;
            hsm[row0 * 65 + col0]           = fmaxf(fmaf(acc[mt][nt][0], W_INV, s_bt[col0]),     0.0f);
            hsm[row0 * 65 + col0 + 1]       = fmaxf(fmaf(acc[mt][nt][1], W_INV, s_bt[col0 + 1]), 0.0f);
            hsm[(row0 + 8) * 65 + col0]     = fmaxf(fmaf(acc[mt][nt][2], W_INV, s_bt[col0]),     0.0f);
            hsm[(row0 + 8) * 65 + col0 + 1] = fmaxf(fmaf(acc[mt][nt][3], W_INV, s_bt[col0 + 1]), 0.0f);
        }
    }
    __syncthreads();

    // ---------------- stage 2: p = sigmoid(h @ w_d + b_d), one row per thread --
    const float* hrow = &hsm[tid * 65];
    float p[NLEAF];
    #pragma unroll
    for (int j = 0; j < NLEAF; j++) p[j] = s_bd[j];
    #pragma unroll
    for (int k = 0; k < NNODE; k++) {
        float hv = hrow[k];
        #pragma unroll
        for (int j = 0; j < NLEAF; j++) p[j] = fmaf(hv, s_wd[k * NLEAF + j], p[j]);
    }
    #pragma unroll
    for (int j = 0; j < NLEAF; j++) p[j] = fast_sigmoid(p[j]);

    // ---------------- stage 3: soft routing + tanh ----------------------------
    float facc = 0.0f;
    #pragma unroll
    for (int l = 0; l < NLEAVES; l++) {
        int node = 0;
        float m = 1.0f;
        #pragma unroll
        for (int d = 0; d < 4; d++) {
            int bit = (l >> (3 - d)) & 1;
            float pv = p[node];
            m *= bit ? (1.0f - pv) : pv;
            node = 2 * node + 1 + bit;
        }
        facc = fmaf(m, s_wl[l], facc);
    }
    float f = tanhf(facc + b_l[t]);
    g_fT[(size_t)(rb + tid) * T_TREES + t] = f;
}

// ---------------- cumsum: one warp per batch row -------------------------------
__global__ void gbdt_cumsum_kernel(const float* __restrict__ f0,
                                   float* __restrict__ out)
{
    int gwarp = (blockIdx.x * blockDim.x + threadIdx.x) >> 5;
    int lane  = threadIdx.x & 31;
    if (gwarp >= BATCH) return;
    float run = f0[0];
    if (lane == 0) out[(size_t)gwarp * (T_TREES + 1)] = run;
    for (int base = 0; base < T_TREES; base += 32) {
        int tt = base + lane;
        float v = (tt < T_TREES) ? LR * g_fT[(size_t)gwarp * T_TREES + tt] : 0.0f;
        #pragma unroll
        for (int off = 1; off < 32; off <<= 1) {
            float nv = __shfl_up_sync(0xFFFFFFFFu, v, off);
            if (lane >= off) v += nv;
        }
        if (tt < T_TREES) out[(size_t)gwarp * (T_TREES + 1) + 1 + tt] = run + v;
        run += __shfl_sync(0xFFFFFFFFu, v, 31);
    }
}

// ---------------- launcher ------------------------------------------------------
extern "C" void kernel_launch(void* const* d_in, const int* in_sizes, int n_in,
                              void* d_out, int out_size)
{
    const float* x   = (const float*)d_in[0];
    const float* w_t = (const float*)d_in[2];
    const float* b_t = (const float*)d_in[3];
    const float* w_d = (const float*)d_in[4];
    const float* b_d = (const float*)d_in[5];
    const float* w_l = (const float*)d_in[6];
    const float* b_l = (const float*)d_in[7];
    const float* f_0 = (const float*)d_in[8];
    float* out = (float*)d_out;

    cudaFuncSetAttribute(gbdt_main_kernel,
                         cudaFuncAttributeMaxDynamicSharedMemorySize, SMEM_DYN);

    conv_x_kernel<<<(BATCH * D_FEAT / 8 + 255) / 256, 256>>>(x);
    conv_w_kernel<<<dim3(D_FEAT / 64, T_TREES), 256>>>(w_t);
    gbdt_main_kernel<<<dim3(BATCH / 128, T_TREES), 128, SMEM_DYN>>>(b_t, w_d, b_d, w_l, b_l);
    gbdt_cumsum_kernel<<<(BATCH * 32 + 255) / 256, 256>>>(f_0, out);
}